// round 16
// baseline (speedup 1.0000x reference)
#include <cuda_runtime.h>
#include <cuda_bf16.h>

// Fixed problem shape
#define B_    4
#define N_    64
#define HW_   512
#define RW_   32     // region width  (one lane per column)
#define RH_   32     // region height (rows accumulated in registers)
#define FULL  0xFFFFFFFFu

__device__ __forceinline__ float ex2(float x) {
    float r;
    asm("ex2.approx.f32 %0, %1;" : "=f"(r) : "f"(x));
    return r;
}

// Warp-autonomous sparse density kernel, single-wave grid (converged design,
// best-measured configuration):
//  - each warp owns a 32x32 output region; lane = column, 32 row-accs in regs
//  - no shared memory, no block barriers
//  - active labels via ballot; label coords via shuffle
//  - analytic normalization sigma*sqrt(2pi) unless border-clipped
//  - gy: one ex2 per lane (lane = row), shuffle-broadcast to all lanes
// grid (16, 2, 4) = 128 blocks x 256 threads -> ONE wave on 148 SMs.
__global__ __launch_bounds__(256) void density_warp2(
    const float* __restrict__ labels,   // (B, N, 2)
    const float* __restrict__ sigma_p,  // scalar
    float* __restrict__ out)            // (B, 1, 512, 512)
{
    const int b    = blockIdx.z;
    const int w0   = blockIdx.x * RW_;
    const int t    = threadIdx.x;
    const int lane = t & 31;
    const int wi   = t >> 5;                      // warp 0..7
    const int h0   = blockIdx.y * 256 + wi * RH_; // this warp's first row

    const float sigma = sigma_p[0];
    const float inv2  = 1.0f / (2.0f * sigma * sigma);
    const float cexp  = -inv2 * 1.4426950408889634f;   // fold log2(e)
    const float R     = 6.5f * sigma;                  // e^{-21} truncation
    const float s_an  = sigma * 2.5066282746310002f;   // sigma*sqrt(2*pi)
    const float inv_an = 1.0f / (s_an * s_an);

    const float xf   = (float)(w0 + lane);
    const float rowf = (float)(h0 + lane);             // lane's gy row

    // broadcast label loads (same 512B for every warp -> L2/L1 after first)
    const float2* lab2 = (const float2*)labels + b * N_;
    float2 p0 = __ldg(&lab2[lane]);
    float2 p1 = __ldg(&lab2[lane + 32]);

    // region-active test (region + R margin)
    const float wlo = (float)w0 - R,  whi = (float)(w0 + RW_ - 1) + R;
    const float hlo = (float)h0 - R,  hhi = (float)(h0 + RH_ - 1) + R;
    bool a0 = (p0.x >= wlo) && (p0.x <= whi) && (p0.y >= hlo) && (p0.y <= hhi);
    bool a1 = (p1.x >= wlo) && (p1.x <= whi) && (p1.y >= hlo) && (p1.y <= hhi);
    unsigned m0 = __ballot_sync(FULL, a0);
    unsigned m1 = __ballot_sync(FULL, a1);

    float acc[RH_];
    #pragma unroll
    for (int r = 0; r < RH_; r++) acc[r] = 0.0f;

    #pragma unroll
    for (int bank = 0; bank < 2; bank++) {
        unsigned m = bank ? m1 : m0;
        const float px = bank ? p1.x : p0.x;
        const float py = bank ? p1.y : p0.y;
        while (m) {                               // uniform across warp
            const int n = __ffs(m) - 1;
            m &= m - 1;
            const float lx = __shfl_sync(FULL, px, n);
            const float ly = __shfl_sync(FULL, py, n);

            // ---- normalization -------------------------------------------
            float inv = inv_an;
            const bool clip = (lx < R) || (lx > 511.0f - R) ||
                              (ly < R) || (ly > 511.0f - R);
            if (clip) {                           // uniform branch (rare)
                // lanes 0-15: x-axis window sum; lanes 16-31: y-axis
                const int axis = lane >> 4;
                const int j    = lane & 15;
                const float l  = axis ? ly : lx;
                float s;
                if (l >= R && l <= 511.0f - R) {
                    s = (j == 0) ? s_an : 0.0f;
                } else {
                    int lo = (int)ceilf(l - R);  if (lo < 0) lo = 0;
                    int hi = (int)floorf(l + R); if (hi > HW_ - 1) hi = HW_ - 1;
                    s = 0.0f;
                    for (int i = lo + j; i <= hi; i += 16) {
                        float d = (float)i - l;
                        s += ex2(d * d * cexp);
                    }
                }
                s += __shfl_xor_sync(FULL, s, 1);
                s += __shfl_xor_sync(FULL, s, 2);
                s += __shfl_xor_sync(FULL, s, 4);
                s += __shfl_xor_sync(FULL, s, 8);
                float so = __shfl_xor_sync(FULL, s, 16);
                inv = 1.0f / (s * so);            // same in every lane
            }

            // ---- gaussians -----------------------------------------------
            float dyr = rowf - ly;                // lane's row
            float gyl = ex2(dyr * dyr * cexp);
            float dx  = xf - lx;                  // lane's column
            float gxi = ex2(dx * dx * cexp) * inv;

            #pragma unroll
            for (int r = 0; r < RH_; r++) {
                float gy = __shfl_sync(FULL, gyl, r);
                acc[r] += gy * gxi;
            }
        }
    }

    // ---- store: 32 warp-coalesced 128B rows ------------------------------
    float* ob = out + ((size_t)b * HW_ + h0) * HW_ + w0 + lane;
    #pragma unroll
    for (int r = 0; r < RH_; r++)
        ob[r * (size_t)HW_] = acc[r];
}

extern "C" void kernel_launch(void* const* d_in, const int* in_sizes, int n_in,
                              void* d_out, int out_size) {
    // d_in[0]: batch_images (unused, shape only)
    // d_in[1]: batch_labels (4,64,2) f32
    // d_in[2]: sigma scalar f32
    const float* labels = (const float*)d_in[1];
    const float* sigma  = (const float*)d_in[2];
    float* out = (float*)d_out;

    dim3 grid(HW_ / RW_, HW_ / 256, B_);   // (16, 2, 4) = 128 blocks, one wave
    density_warp2<<<grid, 256>>>(labels, sigma, out);
}

// round 17
// speedup vs baseline: 1.1244x; 1.1244x over previous
#include <cuda_runtime.h>
#include <cuda_bf16.h>

// Fixed problem shape
#define B_    4
#define N_    64
#define HW_   512
#define RW_   32     // region width  (one lane per column)
#define RH_   32     // region height (rows accumulated in registers)
#define FULL  0xFFFFFFFFu

__device__ __forceinline__ float ex2(float x) {
    float r;
    asm("ex2.approx.f32 %0, %1;" : "=f"(r) : "f"(x));
    return r;
}

// FINAL: warp-autonomous sparse density kernel, single-wave grid.
//  - each warp owns a 32x32 output region; lane = column, 32 row-accs in regs
//  - no shared memory, no block barriers
//  - active labels via ballot; label coords via shuffle
//  - analytic normalization sigma*sqrt(2pi) unless border-clipped
//  - raw ex2.approx (log2e folded); smooth underflow replaces window clamp
// grid (16, 2, 4) = 128 blocks x 256 threads -> ONE wave on 148 SMs.
__global__ __launch_bounds__(256) void density_warp2(
    const float* __restrict__ labels,   // (B, N, 2)
    const float* __restrict__ sigma_p,  // scalar
    float* __restrict__ out)            // (B, 1, 512, 512)
{
    const int b    = blockIdx.z;
    const int w0   = blockIdx.x * RW_;
    const int t    = threadIdx.x;
    const int lane = t & 31;
    const int wi   = t >> 5;                      // warp 0..7
    const int h0   = blockIdx.y * 256 + wi * RH_; // this warp's first row

    const float sigma = sigma_p[0];
    const float inv2  = 1.0f / (2.0f * sigma * sigma);
    const float cexp  = -inv2 * 1.4426950408889634f;   // fold log2(e)
    const float R     = 6.5f * sigma;                  // e^{-21} truncation
    const float s_an  = sigma * 2.5066282746310002f;   // sigma*sqrt(2*pi)
    const float inv_an = 1.0f / (s_an * s_an);

    const float xf   = (float)(w0 + lane);
    const float rowf = (float)(h0 + lane);             // lane's gy row

    // broadcast label loads (same 512B for every warp -> L2/L1 after first)
    const float2* lab2 = (const float2*)labels + b * N_;
    float2 p0 = __ldg(&lab2[lane]);
    float2 p1 = __ldg(&lab2[lane + 32]);

    // region-active test (region + R margin)
    const float wlo = (float)w0 - R,  whi = (float)(w0 + RW_ - 1) + R;
    const float hlo = (float)h0 - R,  hhi = (float)(h0 + RH_ - 1) + R;
    bool a0 = (p0.x >= wlo) && (p0.x <= whi) && (p0.y >= hlo) && (p0.y <= hhi);
    bool a1 = (p1.x >= wlo) && (p1.x <= whi) && (p1.y >= hlo) && (p1.y <= hhi);
    unsigned m0 = __ballot_sync(FULL, a0);
    unsigned m1 = __ballot_sync(FULL, a1);

    float acc[RH_];
    #pragma unroll
    for (int r = 0; r < RH_; r++) acc[r] = 0.0f;

    #pragma unroll
    for (int bank = 0; bank < 2; bank++) {
        unsigned m = bank ? m1 : m0;
        const float px = bank ? p1.x : p0.x;
        const float py = bank ? p1.y : p0.y;
        while (m) {                               // uniform across warp
            const int n = __ffs(m) - 1;
            m &= m - 1;
            const float lx = __shfl_sync(FULL, px, n);
            const float ly = __shfl_sync(FULL, py, n);

            // ---- normalization -------------------------------------------
            float inv = inv_an;
            const bool clip = (lx < R) || (lx > 511.0f - R) ||
                              (ly < R) || (ly > 511.0f - R);
            if (clip) {                           // uniform branch (rare)
                // lanes 0-15: x-axis window sum; lanes 16-31: y-axis
                const int axis = lane >> 4;
                const int j    = lane & 15;
                const float l  = axis ? ly : lx;
                float s;
                if (l >= R && l <= 511.0f - R) {
                    s = (j == 0) ? s_an : 0.0f;
                } else {
                    int lo = (int)ceilf(l - R);  if (lo < 0) lo = 0;
                    int hi = (int)floorf(l + R); if (hi > HW_ - 1) hi = HW_ - 1;
                    s = 0.0f;
                    for (int i = lo + j; i <= hi; i += 16) {
                        float d = (float)i - l;
                        s += ex2(d * d * cexp);
                    }
                }
                s += __shfl_xor_sync(FULL, s, 1);
                s += __shfl_xor_sync(FULL, s, 2);
                s += __shfl_xor_sync(FULL, s, 4);
                s += __shfl_xor_sync(FULL, s, 8);
                float so = __shfl_xor_sync(FULL, s, 16);
                inv = 1.0f / (s * so);            // same in every lane
            }

            // ---- gaussians -----------------------------------------------
            float dyr = rowf - ly;                // lane's row
            float gyl = ex2(dyr * dyr * cexp);
            float dx  = xf - lx;                  // lane's column
            float gxi = ex2(dx * dx * cexp) * inv;

            #pragma unroll
            for (int r = 0; r < RH_; r++) {
                float gy = __shfl_sync(FULL, gyl, r);
                acc[r] += gy * gxi;
            }
        }
    }

    // ---- store: 32 warp-coalesced 128B rows ------------------------------
    float* ob = out + ((size_t)b * HW_ + h0) * HW_ + w0 + lane;
    #pragma unroll
    for (int r = 0; r < RH_; r++)
        ob[r * (size_t)HW_] = acc[r];
}

extern "C" void kernel_launch(void* const* d_in, const int* in_sizes, int n_in,
                              void* d_out, int out_size) {
    // d_in[0]: batch_images (unused, shape only)
    // d_in[1]: batch_labels (4,64,2) f32
    // d_in[2]: sigma scalar f32
    const float* labels = (const float*)d_in[1];
    const float* sigma  = (const float*)d_in[2];
    float* out = (float*)d_out;

    dim3 grid(HW_ / RW_, HW_ / 256, B_);   // (16, 2, 4) = 128 blocks, one wave
    density_warp2<<<grid, 256>>>(labels, sigma, out);
}